// round 8
// baseline (speedup 1.0000x reference)
#include <cuda_runtime.h>

// LSTM_22763326669221 — fused big-batch tiny-LSTM, round 8.
// R7 (1436us): LDS halved (L1 44%) but regs=255 -> 8 warps/SM, issue 45%,
// latency-bound. R8: same unit-split lane pairing, but the per-step h
// exchange goes through a padded smem scratch instead of a register
// array + shfl: -32 regs -> fits launch_bounds(128,3) = 12 warps/SM.

#define SEQB  3
#define BATCH 524288
#define INPD  2
#define HIDD  32
#define NCLS  2
#define FOUT  3

#define THREADS 128
#define HSTRIDE 18   // u64 stride per psg row (16B-aligned, ~2-way conflicts)

typedef unsigned long long u64;

__device__ __forceinline__ u64 ffma2(u64 a, u64 b, u64 c) {
    u64 d;
    asm("fma.rn.f32x2 %0, %1, %2, %3;" : "=l"(d) : "l"(a), "l"(b), "l"(c));
    return d;
}
__device__ __forceinline__ u64 pk(float lo, float hi) {
    u64 r;
    asm("mov.b64 %0, {%1, %2};" : "=l"(r) : "f"(lo), "f"(hi));
    return r;
}
__device__ __forceinline__ void upk(u64 v, float& lo, float& hi) {
    asm("mov.b64 {%0, %1}, %2;" : "=f"(lo), "=f"(hi) : "l"(v));
}
// Opaque pass-through (anti-LICM across time steps).
__device__ __forceinline__ unsigned launder(unsigned a) {
    asm volatile("" : "+r"(a));
    return a;
}
// 16B shared load — plain (reorderable/pipelinable).
__device__ __forceinline__ void lds2(u64& a, u64& b, unsigned addr) {
    asm("ld.shared.v2.b64 {%0, %1}, [%2];"
        : "=l"(a), "=l"(b) : "r"(addr));
}
// volatile variant for the h-exchange readback (must not cross __syncwarp)
__device__ __forceinline__ void lds2v(u64& a, u64& b, unsigned addr) {
    asm volatile("ld.shared.v2.b64 {%0, %1}, [%2];"
                 : "=l"(a), "=l"(b) : "r"(addr));
}
__device__ __forceinline__ u64 lds1(unsigned addr) {
    u64 v;
    asm("ld.shared.b64 %0, [%1];" : "=l"(v) : "r"(addr));
    return v;
}
__device__ __forceinline__ void sts1(unsigned addr, u64 v) {
    asm volatile("st.shared.b64 [%0], %1;" :: "r"(addr), "l"(v));
}
__device__ __forceinline__ float ex2f(float x) {
    float r; asm("ex2.approx.f32 %0, %1;" : "=f"(r) : "f"(x)); return r;
}
__device__ __forceinline__ float rcpf(float x) {
    float r; asm("rcp.approx.f32 %0, %1;" : "=f"(r) : "f"(x)); return r;
}
__device__ __forceinline__ float sigmoidf(float x) {
    float t = ex2f(-1.4426950408889634f * x);
    return rcpf(1.0f + t);
}
__device__ __forceinline__ float tanhf_(float x) {
    float u = ex2f(-2.8853900817779268f * x);
    float r = rcpf(1.0f + u);
    return fmaf(-u, r, r);
}

// Shared layouts (weights identical to R5/R7):
//  sW [P][kp][r], P=0..15 unit pair, r=gate*2+par, row j=(r>>1)*32+2P+(r&1)
//  sIn[P][r][s] : s=0 -> (W_ih[j][0], W_ih[j][1]) ; s=1 -> (b[j], 0)
//  sFC[n][kp]   : (W_fc[n][2kp], W_fc[n][2kp+1]);  sFCb[n] = (b_fc[n], 0)
//  sH [u][psg][HSTRIDE] : per-step h exchange scratch (psg = pair slot 0..63)

__global__ void __launch_bounds__(THREADS, 3)
lstm_fused_kernel(const float* __restrict__ x,
                  const float* __restrict__ W_ih,
                  const float* __restrict__ W_hh,
                  const float* __restrict__ b_ih,
                  const float* __restrict__ b_hh,
                  const float* __restrict__ W_fc,
                  const float* __restrict__ b_fc,
                  float* __restrict__ out) {
    __shared__ __align__(16) u64 sW[16 * 16 * 8];
    __shared__ __align__(16) u64 sIn[16 * 8 * 2];
    __shared__ __align__(16) u64 sFC[2 * 16];
    __shared__ __align__(16) u64 sFCb[2];
    __shared__ __align__(16) u64 sH[2 * 64 * HSTRIDE];

    for (int i = threadIdx.x; i < 16 * 16 * 8; i += THREADS) {
        int r = i & 7, kp = (i >> 3) & 15, P = i >> 7;
        int j = (r >> 1) * 32 + 2 * P + (r & 1);
        sW[i] = pk(W_hh[j * 32 + 2 * kp], W_hh[j * 32 + 2 * kp + 1]);
    }
    for (int i = threadIdx.x; i < 16 * 8 * 2; i += THREADS) {
        int s = i & 1, r = (i >> 1) & 7, P = i >> 4;
        int j = (r >> 1) * 32 + 2 * P + (r & 1);
        sIn[i] = s ? pk(b_ih[j] + b_hh[j], 0.0f)
                   : pk(W_ih[2 * j], W_ih[2 * j + 1]);
    }
    for (int i = threadIdx.x; i < 32; i += THREADS) {
        int n = i >> 4, kp = i & 15;
        sFC[i] = pk(W_fc[n * 32 + 2 * kp], W_fc[n * 32 + 2 * kp + 1]);
    }
    if (threadIdx.x < 2) sFCb[threadIdx.x] = pk(b_fc[threadIdx.x], 0.0f);
    __syncthreads();

    const unsigned sW_a  = (unsigned)__cvta_generic_to_shared(sW);
    const unsigned sIn_a = (unsigned)__cvta_generic_to_shared(sIn);
    const unsigned sFC_a = (unsigned)__cvta_generic_to_shared(sFC);
    const unsigned sFCb_a = (unsigned)__cvta_generic_to_shared(sFCb);
    const unsigned sH_a  = (unsigned)__cvta_generic_to_shared(sH);

    // lane pairing: lanes L and L^16 share the same 2 elements.
    const int lane = threadIdx.x & 31;
    const int half = lane >> 4;              // unit-half owned by this lane
    const int psg  = ((threadIdx.x >> 5) << 4) + (lane & 15);  // 0..63
    const int slot = (int)(blockIdx.x * (THREADS >> 5) + (threadIdx.x >> 5))
                       * 16 + (lane & 15);   // global element-pair id
    const int e0 = slot * 2;                 // elements e0, e0+1

    // per-thread scratch bases: write own half at [u][psg][half*8 + p]
    const unsigned hRow0 = sH_a + (unsigned)(psg * HSTRIDE) * 8;
    const unsigned hRow1 = hRow0 + (unsigned)(64 * HSTRIDE) * 8;
    const unsigned hWr0 = hRow0 + (unsigned)(half * 8) * 8;
    const unsigned hWr1 = hRow1 + (unsigned)(half * 8) * 8;

    const float2* x2 = reinterpret_cast<const float2*>(x);
    u64 d0[2], d1[2], d2[2];
#pragma unroll
    for (int u = 0; u < 2; u++) {
        float2 v0 = x2[0 * BATCH + e0 + u];
        float2 v1 = x2[1 * BATCH + e0 + u];
        float2 v2 = x2[2 * BATCH + e0 + u];
        d0[u] = pk(v0.x, v0.y);
        d1[u] = pk(v1.x, v1.y);
        d2[u] = pk(v2.x, v2.y);
    }

    // h full (both halves); c own half only. No hn array (smem exchange).
    u64 h2[2][16], c2[2][8];
#pragma unroll
    for (int u = 0; u < 2; u++) {
#pragma unroll
        for (int k = 0; k < 16; k++) h2[u][k] = 0ull;
#pragma unroll
        for (int k = 0; k < 8; k++) c2[u][k] = 0ull;
    }

    const unsigned halfOffW = (unsigned)half * 8 * 1024;  // 8 P-slots * 1KB
    const unsigned halfOffI = (unsigned)half * 8 * 128;

    float2* o2 = reinterpret_cast<float2*>(out);

#pragma unroll 1
    for (int f = 0; f < FOUT; f++) {
#pragma unroll 1
        for (int t = 0; t < SEQB; t++) {
            const unsigned wA = launder(sW_a) + halfOffW;
            const unsigned iA = launder(sIn_a) + halfOffI;
            u64 xp[2];
#pragma unroll
            for (int u = 0; u < 2; u++)
                xp[u] = (t == 0) ? d0[u] : ((t == 1) ? d1[u] : d2[u]);
#pragma unroll
            for (int p = 0; p < 8; p++) {       // own 8 unit pairs
                const unsigned wbase = wA + p * 1024;
                const unsigned ibase = iA + p * 128;
                u64 a[2][8];
#pragma unroll
                for (int r = 0; r < 8; r += 2) {
                    u64 wiha, biasa, wihb, biasb;
                    lds2(wiha, biasa, ibase + r * 16);
                    lds2(wihb, biasb, ibase + r * 16 + 16);
#pragma unroll
                    for (int u = 0; u < 2; u++) {
                        a[u][r]     = ffma2(xp[u], wiha, biasa);
                        a[u][r + 1] = ffma2(xp[u], wihb, biasb);
                    }
                }
#pragma unroll
                for (int kp = 0; kp < 16; kp++) {
                    const unsigned ka = wbase + kp * 64;
                    u64 w0, w1, w2, w3;
                    lds2(w0, w1, ka);
                    lds2(w2, w3, ka + 16);
#pragma unroll
                    for (int u = 0; u < 2; u++) {
                        u64 hh = h2[u][kp];
                        a[u][0] = ffma2(hh, w0, a[u][0]);
                        a[u][1] = ffma2(hh, w1, a[u][1]);
                        a[u][2] = ffma2(hh, w2, a[u][2]);
                        a[u][3] = ffma2(hh, w3, a[u][3]);
                    }
                    lds2(w0, w1, ka + 32);
                    lds2(w2, w3, ka + 48);
#pragma unroll
                    for (int u = 0; u < 2; u++) {
                        u64 hh = h2[u][kp];
                        a[u][4] = ffma2(hh, w0, a[u][4]);
                        a[u][5] = ffma2(hh, w1, a[u][5]);
                        a[u][6] = ffma2(hh, w2, a[u][6]);
                        a[u][7] = ffma2(hh, w3, a[u][7]);
                    }
                }
#pragma unroll
                for (int u = 0; u < 2; u++) {
                    float lo, hi;
                    upk(a[u][0], lo, hi); float gi0 = sigmoidf(lo + hi);
                    upk(a[u][1], lo, hi); float gi1 = sigmoidf(lo + hi);
                    upk(a[u][2], lo, hi); float gf0 = sigmoidf(lo + hi);
                    upk(a[u][3], lo, hi); float gf1 = sigmoidf(lo + hi);
                    upk(a[u][4], lo, hi); float gg0 = tanhf_(lo + hi);
                    upk(a[u][5], lo, hi); float gg1 = tanhf_(lo + hi);
                    upk(a[u][6], lo, hi); float go0 = sigmoidf(lo + hi);
                    upk(a[u][7], lo, hi); float go1 = sigmoidf(lo + hi);
                    float c0, c1;
                    upk(c2[u][p], c0, c1);
                    float cn0 = fmaf(gf0, c0, gi0 * gg0);
                    float cn1 = fmaf(gf1, c1, gi1 * gg1);
                    c2[u][p] = pk(cn0, cn1);
                    u64 hnp = pk(go0 * tanhf_(cn0), go1 * tanhf_(cn1));
                    // stash new h pair in the exchange scratch
                    sts1((u == 0 ? hWr0 : hWr1) + p * 8, hnp);
                }
            }
            // exchange: both lanes read back the full 16 pairs per element
            __syncwarp();
#pragma unroll
            for (int u = 0; u < 2; u++) {
                const unsigned rbase = (u == 0 ? hRow0 : hRow1);
#pragma unroll
                for (int k = 0; k < 16; k += 2)
                    lds2v(h2[u][k], h2[u][k + 1], rbase + k * 8);
            }
            __syncwarp();   // protect scratch from next step's writes
        }
        // FC head (both lanes compute — result feeds the window; half 0 stores)
        const unsigned fA  = launder(sFC_a);
        const unsigned fbA = launder(sFCb_a);
        u64 acc0[2], acc1[2];
#pragma unroll
        for (int u = 0; u < 2; u++) {
            acc0[u] = lds1(fbA);
            acc1[u] = lds1(fbA + 8);
        }
#pragma unroll
        for (int kp = 0; kp < 16; kp += 2) {
            u64 w0, w1, w2, w3;
            lds2(w0, w1, fA + kp * 8);
            lds2(w2, w3, fA + 128 + kp * 8);
#pragma unroll
            for (int u = 0; u < 2; u++) {
                acc0[u] = ffma2(h2[u][kp], w0, acc0[u]);
                acc0[u] = ffma2(h2[u][kp + 1], w1, acc0[u]);
                acc1[u] = ffma2(h2[u][kp], w2, acc1[u]);
                acc1[u] = ffma2(h2[u][kp + 1], w3, acc1[u]);
            }
        }
#pragma unroll
        for (int u = 0; u < 2; u++) {
            float p0, q0, p1, q1;
            upk(acc0[u], p0, q0);
            upk(acc1[u], p1, q1);
            float out0 = p0 + q0;
            float out1 = p1 + q1;
            if (half == 0)
                o2[f * BATCH + e0 + u] = make_float2(out0, out1);
            // window update: data <- [data[2], data[1], output]
            d0[u] = d2[u];
            d2[u] = pk(out0, out1);
        }
    }
}

extern "C" void kernel_launch(void* const* d_in, const int* in_sizes, int n_in,
                              void* d_out, int out_size) {
    const float* x    = (const float*)d_in[0];
    const float* W_ih = (const float*)d_in[1];
    const float* W_hh = (const float*)d_in[2];
    const float* b_ih = (const float*)d_in[3];
    const float* b_hh = (const float*)d_in[4];
    const float* W_fc = (const float*)d_in[5];
    const float* b_fc = (const float*)d_in[6];
    float* out = (float*)d_out;

    dim3 grid(BATCH / THREADS);
    lstm_fused_kernel<<<grid, THREADS>>>(x, W_ih, W_hh, b_ih, b_hh, W_fc, b_fc, out);
}

// round 9
// speedup vs baseline: 1.0862x; 1.0862x over previous
#include <cuda_runtime.h>

// LSTM_22763326669221 — fused big-batch tiny-LSTM, round 9.
// Base = R5 (best, 1431us). Change: HW tanh.approx.f32 for all
// activations. sigmoid(x) = 0.5*tanh(0.5x)+0.5. MUFU per unit-step
// 10 -> 5, kills the ex2->rcp 32cyc serial chains that dominated the
// per-p epilogue latency (R7/R8 showed occupancy & LDS volume are not
// the wall; per-warp stall structure is).

#define SEQB  3
#define BATCH 524288
#define INPD  2
#define HIDD  32
#define NCLS  2
#define FOUT  3

#define THREADS 128

typedef unsigned long long u64;

__device__ __forceinline__ u64 ffma2(u64 a, u64 b, u64 c) {
    u64 d;
    asm("fma.rn.f32x2 %0, %1, %2, %3;" : "=l"(d) : "l"(a), "l"(b), "l"(c));
    return d;
}
__device__ __forceinline__ u64 pk(float lo, float hi) {
    u64 r;
    asm("mov.b64 %0, {%1, %2};" : "=l"(r) : "f"(lo), "f"(hi));
    return r;
}
__device__ __forceinline__ void upk(u64 v, float& lo, float& hi) {
    asm("mov.b64 {%0, %1}, %2;" : "=f"(lo), "=f"(hi) : "l"(v));
}
// Opaque pass-through (anti-LICM across time steps).
__device__ __forceinline__ unsigned launder(unsigned a) {
    asm volatile("" : "+r"(a));
    return a;
}
// 16B shared load — plain (reorderable/pipelinable).
__device__ __forceinline__ void lds2(u64& a, u64& b, unsigned addr) {
    asm("ld.shared.v2.b64 {%0, %1}, [%2];"
        : "=l"(a), "=l"(b) : "r"(addr));
}
__device__ __forceinline__ u64 lds1(unsigned addr) {
    u64 v;
    asm("ld.shared.b64 %0, [%1];" : "=l"(v) : "r"(addr));
    return v;
}
// HW tanh: single MUFU op (sm_75+), ~1e-5 abs err.
__device__ __forceinline__ float tanh_hw(float x) {
    float r; asm("tanh.approx.f32 %0, %1;" : "=f"(r) : "f"(x)); return r;
}
// sigmoid(x) = 0.5*tanh(0.5x) + 0.5  -> fma + MUFU + fma
__device__ __forceinline__ float sigmoid_hw(float x) {
    return fmaf(0.5f, tanh_hw(0.5f * x), 0.5f);
}

// Shared layouts (u64 pair-packed, even/odd hidden units):
//  sW [p][kp][r], r = gate*2+par (gates i,f,g,o), row j = gate*32+2p+(r&1)
//  sIn[p][r][s] : s=0 -> (W_ih[j][0], W_ih[j][1]) ; s=1 -> (b[j], 0)
//  sFC[n][kp]   : (W_fc[n][2kp], W_fc[n][2kp+1]);  sFCb[n] = (b_fc[n], 0)

__global__ void __launch_bounds__(THREADS, 3)
lstm_fused_kernel(const float* __restrict__ x,
                  const float* __restrict__ W_ih,
                  const float* __restrict__ W_hh,
                  const float* __restrict__ b_ih,
                  const float* __restrict__ b_hh,
                  const float* __restrict__ W_fc,
                  const float* __restrict__ b_fc,
                  float* __restrict__ out) {
    __shared__ __align__(16) u64 sW[16 * 16 * 8];
    __shared__ __align__(16) u64 sIn[16 * 8 * 2];
    __shared__ __align__(16) u64 sFC[2 * 16];
    __shared__ __align__(16) u64 sFCb[2];

    for (int i = threadIdx.x; i < 16 * 16 * 8; i += THREADS) {
        int r = i & 7, kp = (i >> 3) & 15, p = i >> 7;
        int j = (r >> 1) * 32 + 2 * p + (r & 1);
        sW[i] = pk(W_hh[j * 32 + 2 * kp], W_hh[j * 32 + 2 * kp + 1]);
    }
    for (int i = threadIdx.x; i < 16 * 8 * 2; i += THREADS) {
        int s = i & 1, r = (i >> 1) & 7, p = i >> 4;
        int j = (r >> 1) * 32 + 2 * p + (r & 1);
        sIn[i] = s ? pk(b_ih[j] + b_hh[j], 0.0f)
                   : pk(W_ih[2 * j], W_ih[2 * j + 1]);
    }
    for (int i = threadIdx.x; i < 32; i += THREADS) {
        int n = i >> 4, kp = i & 15;
        sFC[i] = pk(W_fc[n * 32 + 2 * kp], W_fc[n * 32 + 2 * kp + 1]);
    }
    if (threadIdx.x < 2) sFCb[threadIdx.x] = pk(b_fc[threadIdx.x], 0.0f);
    __syncthreads();

    const unsigned sW_a  = (unsigned)__cvta_generic_to_shared(sW);
    const unsigned sIn_a = (unsigned)__cvta_generic_to_shared(sIn);
    const unsigned sFC_a = (unsigned)__cvta_generic_to_shared(sFC);
    const unsigned sFCb_a = (unsigned)__cvta_generic_to_shared(sFCb);

    const int e = blockIdx.x * THREADS + threadIdx.x;  // batch element

    const float2* x2 = reinterpret_cast<const float2*>(x);
    float2 v0 = x2[0 * BATCH + e];
    float2 v1 = x2[1 * BATCH + e];
    float2 v2 = x2[2 * BATCH + e];
    u64 d0 = pk(v0.x, v0.y);
    u64 d1 = pk(v1.x, v1.y);
    u64 d2 = pk(v2.x, v2.y);

    u64 h2[16], hn[16], c2[16];
#pragma unroll
    for (int k = 0; k < 16; k++) { h2[k] = 0ull; c2[k] = 0ull; }

    float2* o2 = reinterpret_cast<float2*>(out);

#pragma unroll 1
    for (int f = 0; f < FOUT; f++) {
#pragma unroll 1
        for (int t = 0; t < SEQB; t++) {
            // Fresh (opaque) base addresses each step: loads below cannot be
            // hoisted or CSE'd across steps, but CAN be pipelined within one.
            const unsigned wA = launder(sW_a);
            const unsigned iA = launder(sIn_a);
            u64 xp = (t == 0) ? d0 : ((t == 1) ? d1 : d2);
#pragma unroll
            for (int p = 0; p < 16; p++) {
                const unsigned wbase = wA + p * 1024;   // 16 kp * 8 r * 8B
                const unsigned ibase = iA + p * 128;    // 8 r * 2 s * 8B
                u64 wih, bias;
                // accumulator init: lane.x = x0*wih0 + b ; lane.y = x1*wih1
                lds2(wih, bias, ibase + 0);   u64 a0 = ffma2(xp, wih, bias);
                lds2(wih, bias, ibase + 16);  u64 a1 = ffma2(xp, wih, bias);
                lds2(wih, bias, ibase + 32);  u64 a2 = ffma2(xp, wih, bias);
                lds2(wih, bias, ibase + 48);  u64 a3 = ffma2(xp, wih, bias);
                lds2(wih, bias, ibase + 64);  u64 a4 = ffma2(xp, wih, bias);
                lds2(wih, bias, ibase + 80);  u64 a5 = ffma2(xp, wih, bias);
                lds2(wih, bias, ibase + 96);  u64 a6 = ffma2(xp, wih, bias);
                lds2(wih, bias, ibase + 112); u64 a7 = ffma2(xp, wih, bias);
#pragma unroll
                for (int kp = 0; kp < 16; kp++) {
                    const unsigned ka = wbase + kp * 64;
                    u64 hh = h2[kp];
                    u64 w0, w1, w2, w3;
                    lds2(w0, w1, ka);
                    lds2(w2, w3, ka + 16);
                    a0 = ffma2(hh, w0, a0);
                    a1 = ffma2(hh, w1, a1);
                    a2 = ffma2(hh, w2, a2);
                    a3 = ffma2(hh, w3, a3);
                    lds2(w0, w1, ka + 32);
                    lds2(w2, w3, ka + 48);
                    a4 = ffma2(hh, w0, a4);
                    a5 = ffma2(hh, w1, a5);
                    a6 = ffma2(hh, w2, a6);
                    a7 = ffma2(hh, w3, a7);
                }
                float lo, hi;
                upk(a0, lo, hi); float gi0 = sigmoid_hw(lo + hi);
                upk(a1, lo, hi); float gi1 = sigmoid_hw(lo + hi);
                upk(a2, lo, hi); float gf0 = sigmoid_hw(lo + hi);
                upk(a3, lo, hi); float gf1 = sigmoid_hw(lo + hi);
                upk(a4, lo, hi); float gg0 = tanh_hw(lo + hi);
                upk(a5, lo, hi); float gg1 = tanh_hw(lo + hi);
                upk(a6, lo, hi); float go0 = sigmoid_hw(lo + hi);
                upk(a7, lo, hi); float go1 = sigmoid_hw(lo + hi);
                float c0, c1;
                upk(c2[p], c0, c1);
                float cn0 = fmaf(gf0, c0, gi0 * gg0);
                float cn1 = fmaf(gf1, c1, gi1 * gg1);
                c2[p] = pk(cn0, cn1);
                hn[p] = pk(go0 * tanh_hw(cn0), go1 * tanh_hw(cn1));
            }
#pragma unroll
            for (int k = 0; k < 16; k++) h2[k] = hn[k];
        }
        // FC head: out[n] = b_fc[n] + h . W_fc[n]
        const unsigned fA  = launder(sFC_a);
        const unsigned fbA = launder(sFCb_a);
        u64 a0 = lds1(fbA);
        u64 a1 = lds1(fbA + 8);
#pragma unroll
        for (int kp = 0; kp < 16; kp += 2) {
            u64 w0, w1;
            lds2(w0, w1, fA + kp * 8);
            a0 = ffma2(h2[kp], w0, a0);
            a0 = ffma2(h2[kp + 1], w1, a0);
            lds2(w0, w1, fA + 128 + kp * 8);
            a1 = ffma2(h2[kp], w0, a1);
            a1 = ffma2(h2[kp + 1], w1, a1);
        }
        float p0, q0, p1, q1;
        upk(a0, p0, q0);
        upk(a1, p1, q1);
        float out0 = p0 + q0;
        float out1 = p1 + q1;
        o2[f * BATCH + e] = make_float2(out0, out1);
        // window update: data <- [data[2], data[1], output]
        d0 = d2;
        d2 = pk(out0, out1);
    }
}

extern "C" void kernel_launch(void* const* d_in, const int* in_sizes, int n_in,
                              void* d_out, int out_size) {
    const float* x    = (const float*)d_in[0];
    const float* W_ih = (const float*)d_in[1];
    const float* W_hh = (const float*)d_in[2];
    const float* b_ih = (const float*)d_in[3];
    const float* b_hh = (const float*)d_in[4];
    const float* W_fc = (const float*)d_in[5];
    const float* b_fc = (const float*)d_in[6];
    float* out = (float*)d_out;

    dim3 grid(BATCH / THREADS);
    lstm_fused_kernel<<<grid, THREADS>>>(x, W_ih, W_hh, b_ih, b_hh, W_fc, b_fc, out);
}

// round 11
// speedup vs baseline: 1.3137x; 1.2094x over previous
#include <cuda_runtime.h>

// LSTM_22763326669221 — fused big-batch tiny-LSTM, round 11.
// (Re-bench of round-10 design: R10 failed on broker infrastructure, not
// on the kernel — same as R3.)
// R10/R11 = R7 structure + R9 activations, combining the two proven wins:
//  - R7 unit-split lane pairing: lanes L and L^16 cooperate, each computes
//    half the hidden units for TWO elements -> weight LDS per FLOP halved
//    (L1 was 44% vs 86%).
//  - R9 hardware tanh.approx: 1 MUFU per activation, sigmoid via
//    0.5*tanh(0.5x)+0.5 -> the per-p epilogue serial chains (R7's actual
//    wall, issue=45%) are halved.

#define SEQB  3
#define BATCH 524288
#define INPD  2
#define HIDD  32
#define NCLS  2
#define FOUT  3

#define THREADS 128

typedef unsigned long long u64;

__device__ __forceinline__ u64 ffma2(u64 a, u64 b, u64 c) {
    u64 d;
    asm("fma.rn.f32x2 %0, %1, %2, %3;" : "=l"(d) : "l"(a), "l"(b), "l"(c));
    return d;
}
__device__ __forceinline__ u64 pk(float lo, float hi) {
    u64 r;
    asm("mov.b64 %0, {%1, %2};" : "=l"(r) : "f"(lo), "f"(hi));
    return r;
}
__device__ __forceinline__ void upk(u64 v, float& lo, float& hi) {
    asm("mov.b64 {%0, %1}, %2;" : "=f"(lo), "=f"(hi) : "l"(v));
}
// Opaque pass-through (anti-LICM across time steps).
__device__ __forceinline__ unsigned launder(unsigned a) {
    asm volatile("" : "+r"(a));
    return a;
}
// 16B shared load — plain (reorderable/pipelinable).
__device__ __forceinline__ void lds2(u64& a, u64& b, unsigned addr) {
    asm("ld.shared.v2.b64 {%0, %1}, [%2];"
        : "=l"(a), "=l"(b) : "r"(addr));
}
__device__ __forceinline__ u64 lds1(unsigned addr) {
    u64 v;
    asm("ld.shared.b64 %0, [%1];" : "=l"(v) : "r"(addr));
    return v;
}
// butterfly-16 exchange of a packed u64 (two 32-bit shfls)
__device__ __forceinline__ u64 shfl16(u64 v) {
    u64 r;
    asm("{\n\t"
        ".reg .b32 a, b;\n\t"
        "mov.b64 {a, b}, %1;\n\t"
        "shfl.sync.bfly.b32 a, a, 16, 0x1f, 0xffffffff;\n\t"
        "shfl.sync.bfly.b32 b, b, 16, 0x1f, 0xffffffff;\n\t"
        "mov.b64 %0, {a, b};\n\t"
        "}" : "=l"(r) : "l"(v));
    return r;
}
// HW tanh: single MUFU op (sm_75+), ~1e-5 abs err.
__device__ __forceinline__ float tanh_hw(float x) {
    float r; asm("tanh.approx.f32 %0, %1;" : "=f"(r) : "f"(x)); return r;
}
// sigmoid(x) = 0.5*tanh(0.5x) + 0.5  -> fma + MUFU + fma
__device__ __forceinline__ float sigmoid_hw(float x) {
    return fmaf(0.5f, tanh_hw(0.5f * x), 0.5f);
}

// Shared layouts (identical to R5/R7):
//  sW [P][kp][r], P=0..15 unit pair, r=gate*2+par, row j=(r>>1)*32+2P+(r&1)
//  sIn[P][r][s] : s=0 -> (W_ih[j][0], W_ih[j][1]) ; s=1 -> (b[j], 0)
//  sFC[n][kp]   : (W_fc[n][2kp], W_fc[n][2kp+1]);  sFCb[n] = (b_fc[n], 0)

__global__ void __launch_bounds__(THREADS, 2)
lstm_fused_kernel(const float* __restrict__ x,
                  const float* __restrict__ W_ih,
                  const float* __restrict__ W_hh,
                  const float* __restrict__ b_ih,
                  const float* __restrict__ b_hh,
                  const float* __restrict__ W_fc,
                  const float* __restrict__ b_fc,
                  float* __restrict__ out) {
    __shared__ __align__(16) u64 sW[16 * 16 * 8];
    __shared__ __align__(16) u64 sIn[16 * 8 * 2];
    __shared__ __align__(16) u64 sFC[2 * 16];
    __shared__ __align__(16) u64 sFCb[2];

    for (int i = threadIdx.x; i < 16 * 16 * 8; i += THREADS) {
        int r = i & 7, kp = (i >> 3) & 15, P = i >> 7;
        int j = (r >> 1) * 32 + 2 * P + (r & 1);
        sW[i] = pk(W_hh[j * 32 + 2 * kp], W_hh[j * 32 + 2 * kp + 1]);
    }
    for (int i = threadIdx.x; i < 16 * 8 * 2; i += THREADS) {
        int s = i & 1, r = (i >> 1) & 7, P = i >> 4;
        int j = (r >> 1) * 32 + 2 * P + (r & 1);
        sIn[i] = s ? pk(b_ih[j] + b_hh[j], 0.0f)
                   : pk(W_ih[2 * j], W_ih[2 * j + 1]);
    }
    for (int i = threadIdx.x; i < 32; i += THREADS) {
        int n = i >> 4, kp = i & 15;
        sFC[i] = pk(W_fc[n * 32 + 2 * kp], W_fc[n * 32 + 2 * kp + 1]);
    }
    if (threadIdx.x < 2) sFCb[threadIdx.x] = pk(b_fc[threadIdx.x], 0.0f);
    __syncthreads();

    const unsigned sW_a  = (unsigned)__cvta_generic_to_shared(sW);
    const unsigned sIn_a = (unsigned)__cvta_generic_to_shared(sIn);
    const unsigned sFC_a = (unsigned)__cvta_generic_to_shared(sFC);
    const unsigned sFCb_a = (unsigned)__cvta_generic_to_shared(sFCb);

    // lane pairing: lanes L and L^16 share the same 2 elements.
    const int lane  = threadIdx.x & 31;
    const int half  = lane >> 4;             // which unit-half this lane owns
    const int slot  = ((blockIdx.x * THREADS + threadIdx.x) >> 5) * 16
                      + (lane & 15);         // element pair id
    const int e0 = slot * 2;                 // elements e0, e0+1

    const float2* x2 = reinterpret_cast<const float2*>(x);
    u64 d0[2], d1[2], d2[2];
#pragma unroll
    for (int u = 0; u < 2; u++) {
        float2 v0 = x2[0 * BATCH + e0 + u];
        float2 v1 = x2[1 * BATCH + e0 + u];
        float2 v2 = x2[2 * BATCH + e0 + u];
        d0[u] = pk(v0.x, v0.y);
        d1[u] = pk(v1.x, v1.y);
        d2[u] = pk(v2.x, v2.y);
    }

    // h full (both halves, needed for dot products); c & hn own half only.
    u64 h2[2][16], hn[2][8], c2[2][8];
#pragma unroll
    for (int u = 0; u < 2; u++) {
#pragma unroll
        for (int k = 0; k < 16; k++) h2[u][k] = 0ull;
#pragma unroll
        for (int k = 0; k < 8; k++) c2[u][k] = 0ull;
    }

    const unsigned halfOffW = (unsigned)half * 8 * 1024;  // 8 P-slots * 1KB
    const unsigned halfOffI = (unsigned)half * 8 * 128;

    float2* o2 = reinterpret_cast<float2*>(out);

#pragma unroll 1
    for (int f = 0; f < FOUT; f++) {
#pragma unroll 1
        for (int t = 0; t < SEQB; t++) {
            const unsigned wA = launder(sW_a) + halfOffW;
            const unsigned iA = launder(sIn_a) + halfOffI;
            u64 xp[2];
#pragma unroll
            for (int u = 0; u < 2; u++)
                xp[u] = (t == 0) ? d0[u] : ((t == 1) ? d1[u] : d2[u]);
#pragma unroll
            for (int p = 0; p < 8; p++) {       // own 8 unit pairs
                const unsigned wbase = wA + p * 1024;
                const unsigned ibase = iA + p * 128;
                u64 a[2][8];
#pragma unroll
                for (int r = 0; r < 8; r += 2) {
                    u64 wiha, biasa, wihb, biasb;
                    lds2(wiha, biasa, ibase + r * 16);
                    lds2(wihb, biasb, ibase + r * 16 + 16);
#pragma unroll
                    for (int u = 0; u < 2; u++) {
                        a[u][r]     = ffma2(xp[u], wiha, biasa);
                        a[u][r + 1] = ffma2(xp[u], wihb, biasb);
                    }
                }
#pragma unroll
                for (int kp = 0; kp < 16; kp++) {
                    const unsigned ka = wbase + kp * 64;
                    u64 w0, w1, w2, w3;
                    lds2(w0, w1, ka);
                    lds2(w2, w3, ka + 16);
#pragma unroll
                    for (int u = 0; u < 2; u++) {
                        u64 hh = h2[u][kp];
                        a[u][0] = ffma2(hh, w0, a[u][0]);
                        a[u][1] = ffma2(hh, w1, a[u][1]);
                        a[u][2] = ffma2(hh, w2, a[u][2]);
                        a[u][3] = ffma2(hh, w3, a[u][3]);
                    }
                    lds2(w0, w1, ka + 32);
                    lds2(w2, w3, ka + 48);
#pragma unroll
                    for (int u = 0; u < 2; u++) {
                        u64 hh = h2[u][kp];
                        a[u][4] = ffma2(hh, w0, a[u][4]);
                        a[u][5] = ffma2(hh, w1, a[u][5]);
                        a[u][6] = ffma2(hh, w2, a[u][6]);
                        a[u][7] = ffma2(hh, w3, a[u][7]);
                    }
                }
#pragma unroll
                for (int u = 0; u < 2; u++) {
                    float lo, hi;
                    upk(a[u][0], lo, hi); float gi0 = sigmoid_hw(lo + hi);
                    upk(a[u][1], lo, hi); float gi1 = sigmoid_hw(lo + hi);
                    upk(a[u][2], lo, hi); float gf0 = sigmoid_hw(lo + hi);
                    upk(a[u][3], lo, hi); float gf1 = sigmoid_hw(lo + hi);
                    upk(a[u][4], lo, hi); float gg0 = tanh_hw(lo + hi);
                    upk(a[u][5], lo, hi); float gg1 = tanh_hw(lo + hi);
                    upk(a[u][6], lo, hi); float go0 = sigmoid_hw(lo + hi);
                    upk(a[u][7], lo, hi); float go1 = sigmoid_hw(lo + hi);
                    float c0, c1;
                    upk(c2[u][p], c0, c1);
                    float cn0 = fmaf(gf0, c0, gi0 * gg0);
                    float cn1 = fmaf(gf1, c1, gi1 * gg1);
                    c2[u][p] = pk(cn0, cn1);
                    hn[u][p] = pk(go0 * tanh_hw(cn0), go1 * tanh_hw(cn1));
                }
            }
            // commit: own half direct, partner half via bfly-16 exchange
#pragma unroll
            for (int u = 0; u < 2; u++) {
#pragma unroll
                for (int j = 0; j < 8; j++) {
                    u64 other = shfl16(hn[u][j]);
                    if (half == 0) {
                        h2[u][j]     = hn[u][j];
                        h2[u][8 + j] = other;
                    } else {
                        h2[u][8 + j] = hn[u][j];
                        h2[u][j]     = other;
                    }
                }
            }
        }
        // FC head (both lanes compute — result feeds the window; half 0 stores)
        const unsigned fA  = launder(sFC_a);
        const unsigned fbA = launder(sFCb_a);
        u64 acc0[2], acc1[2];
#pragma unroll
        for (int u = 0; u < 2; u++) {
            acc0[u] = lds1(fbA);
            acc1[u] = lds1(fbA + 8);
        }
#pragma unroll
        for (int kp = 0; kp < 16; kp += 2) {
            u64 w0, w1, w2, w3;
            lds2(w0, w1, fA + kp * 8);
            lds2(w2, w3, fA + 128 + kp * 8);
#pragma unroll
            for (int u = 0; u < 2; u++) {
                acc0[u] = ffma2(h2[u][kp], w0, acc0[u]);
                acc0[u] = ffma2(h2[u][kp + 1], w1, acc0[u]);
                acc1[u] = ffma2(h2[u][kp], w2, acc1[u]);
                acc1[u] = ffma2(h2[u][kp + 1], w3, acc1[u]);
            }
        }
#pragma unroll
        for (int u = 0; u < 2; u++) {
            float p0, q0, p1, q1;
            upk(acc0[u], p0, q0);
            upk(acc1[u], p1, q1);
            float out0 = p0 + q0;
            float out1 = p1 + q1;
            if (half == 0)
                o2[f * BATCH + e0 + u] = make_float2(out0, out1);
            // window update: data <- [data[2], data[1], output]
            d0[u] = d2[u];
            d2[u] = pk(out0, out1);
        }
    }
}

extern "C" void kernel_launch(void* const* d_in, const int* in_sizes, int n_in,
                              void* d_out, int out_size) {
    const float* x    = (const float*)d_in[0];
    const float* W_ih = (const float*)d_in[1];
    const float* W_hh = (const float*)d_in[2];
    const float* b_ih = (const float*)d_in[3];
    const float* b_hh = (const float*)d_in[4];
    const float* W_fc = (const float*)d_in[5];
    const float* b_fc = (const float*)d_in[6];
    float* out = (float*)d_out;

    dim3 grid(BATCH / THREADS);   // 2 lanes x half-units each -> 1 elem/thread equiv
    lstm_fused_kernel<<<grid, THREADS>>>(x, W_ih, W_hh, b_ih, b_hh, W_fc, b_fc, out);
}

// round 13
// speedup vs baseline: 2.7424x; 2.0876x over previous
#include <cuda_runtime.h>
#include <cuda_bf16.h>
#include <cstdint>

// LSTM_22763326669221 — round 13: warp-level tensor cores via mma.sync
// (sm_80-baseline PTX; tcgen05 is compute_100a-only and the harness builds
// at compute_100 — R12's lesson).
// One warp = 16 batch elements, persistent across all 9 steps. Per step:
//   D[16 elem, 128 gates] = A[16, K=112] x B^T   (m16n8k16 bf16, f32 acc)
// bf16 3-term split: A=[hi|hi|lo], B=[Whi|Wlo|Whi]  (err ~2^-17),
// bias folded as an A==1 column. B blocked 8x8 in smem (built once,
// conflict-free ldmatrix.x4); A staged per-warp per-step (STS + syncwarp,
// no CTA syncs in the main loop). Gate columns j,32+j,64+j,96+j land in
// the SAME lane -> lane-local epilogue; FC head via 2 shfl.bfly levels.

#define SEQB   3
#define BATCH  524288
#define FOUT   3
#define THREADS 128

typedef uint32_t u32;

__device__ __forceinline__ u32 smem_u32(const void* p) {
    u32 a;
    asm("{ .reg .u64 t; cvta.to.shared.u64 t, %1; cvt.u32.u64 %0, t; }"
        : "=r"(a) : "l"(p));
    return a;
}
__device__ __forceinline__ float tanh_hw(float x) {
    float r; asm("tanh.approx.f32 %0, %1;" : "=f"(r) : "f"(x)); return r;
}
__device__ __forceinline__ float sigmoid_hw(float x) {
    return fmaf(0.5f, tanh_hw(0.5f * x), 0.5f);
}
// pack: v0 -> low bf16 (lower k slot), v1 -> high bf16
__device__ __forceinline__ u32 pk_bf2(float v0, float v1) {
    u32 d; asm("cvt.rn.bf16x2.f32 %0, %1, %2;" : "=r"(d) : "f"(v1), "f"(v0));
    return d;
}
// split (v0,v1) into bf16 hi pair + bf16 residual (lo) pair
__device__ __forceinline__ void split2(float v0, float v1, u32& hi, u32& lo) {
    hi = pk_bf2(v0, v1);
    float r0 = v0 - __uint_as_float(hi << 16);
    float r1 = v1 - __uint_as_float(hi & 0xffff0000u);
    lo = pk_bf2(r0, r1);
}
__device__ __forceinline__ void sts32(u32 addr, u32 v) {
    asm volatile("st.shared.b32 [%0], %1;" :: "r"(addr), "r"(v) : "memory");
}

#define LDSM4(r0, r1, r2, r3, a) \
    asm volatile("ldmatrix.sync.aligned.m8n8.x4.shared.b16 {%0,%1,%2,%3}, [%4];" \
                 : "=r"(r0), "=r"(r1), "=r"(r2), "=r"(r3) : "r"(a))

#define MMA(dp, a0, a1, a2, a3, b0, b1) \
    asm volatile("mma.sync.aligned.m16n8k16.row.col.f32.bf16.bf16.f32 " \
                 "{%0,%1,%2,%3},{%4,%5,%6,%7},{%8,%9},{%0,%1,%2,%3};" \
                 : "+f"((dp)[0]), "+f"((dp)[1]), "+f"((dp)[2]), "+f"((dp)[3]) \
                 : "r"(a0), "r"(a1), "r"(a2), "r"(a3), "r"(b0), "r"(b1))

// K layout (112 = 14 k8-tiles):
//   seg0 k0-35 : A=hi [x0,x1,1,pad,h0..h31], B=W hi
//   seg1 k36-71: A=hi (duplicate),           B=W lo
//   seg2 k72-107: A=lo residuals (1->0),     B=W hi
//   k108-111: zero pad (A and B both zero)
// B smem: 16 ntiles x 14 ktiles 8x8 blocks, 128B each, offset
//   ((n>>3)*14 + (k>>3))*128 + (n&7)*16 + (k&7)*2
// A smem (per warp): 2 rtiles x 14 ktiles same block scheme.

__global__ void __launch_bounds__(THREADS)
lstm_mma_kernel(const float* __restrict__ x,
                const float* __restrict__ W_ih,
                const float* __restrict__ W_hh,
                const float* __restrict__ b_ih,
                const float* __restrict__ b_hh,
                const float* __restrict__ W_fc,
                const float* __restrict__ b_fc,
                float* __restrict__ out) {
    __shared__ __align__(16) char sB[16 * 14 * 128];      // 28672 B
    __shared__ __align__(16) char sA[4][2 * 14 * 128];    // 4 x 3584 B
    __shared__ float sFC[2][32];
    __shared__ float sFCb2[2];

    const int tid  = threadIdx.x;
    const int w    = tid >> 5;
    const int lane = tid & 31;
    const int g    = lane >> 2;      // group id (D row)
    const int t    = lane & 3;       // thread-in-group (D col pair)

    // ---- zero smem, then fill ----
    for (int i = tid; i < (16 * 14 * 128) / 4; i += THREADS)
        reinterpret_cast<u32*>(sB)[i] = 0;
    for (int i = tid; i < (4 * 2 * 14 * 128) / 4; i += THREADS)
        reinterpret_cast<u32*>(&sA[0][0])[i] = 0;
    __syncthreads();

    {   // B fill: one thread per gate row n
        const int n = tid;
        auto put = [&](int k, uint16_t v) {
            *reinterpret_cast<uint16_t*>(
                sB + ((n >> 3) * 14 + (k >> 3)) * 128 + (n & 7) * 16 + (k & 7) * 2) = v;
        };
        for (int s = 0; s < 36; s++) {
            float wv = (s == 0) ? W_ih[2 * n]
                     : (s == 1) ? W_ih[2 * n + 1]
                     : (s == 2) ? (b_ih[n] + b_hh[n])
                     : (s == 3) ? 0.0f
                     : W_hh[n * 32 + (s - 4)];
            __nv_bfloat16 hb = __float2bfloat16(wv);
            float hf = __bfloat162float(hb);
            __nv_bfloat16 lb = __float2bfloat16(wv - hf);
            uint16_t hbits = __bfloat16_as_ushort(hb);
            uint16_t lbits = __bfloat16_as_ushort(lb);
            put(s, hbits);
            put(72 + s, hbits == hbits ? hbits : hbits);  // seg2 uses W hi
            put(36 + s, lbits);
        }
    }
    if (tid < 64) sFC[tid >> 5][tid & 31] = W_fc[tid];
    if (tid < 2)  sFCb2[tid] = b_fc[tid];
    // A static: 1.0 at k=2 (seg0 bias col) and k=38 (seg1); k=74 stays 0.
    if (t == 0) {
        for (int rr = 0; rr < 2; rr++) {
            char* base = sA[w] + rr * 1792 + g * 16;
            *reinterpret_cast<uint16_t*>(base + 4)             = 0x3F80;  // k=2
            *reinterpret_cast<uint16_t*>(base + 4 * 128 + 12)  = 0x3F80;  // k=38
        }
    }
    __syncthreads();

    // ---- per-lane addresses ----
    const u32 sB_a = smem_u32(sB);
    const u32 aW   = smem_u32(sA[w]);
    const int msel = lane >> 3, rowin = lane & 7;
    // A x4 order: (rt0,kt0),(rt1,kt0),(rt0,kt1),(rt1,kt1)
    const u32 addrA0 = aW + (u32)(((msel & 1) * 14 + (msel >> 1)) * 128 + rowin * 16);
    // B x4 order: (nt0,kt0),(nt0,kt1),(nt1,kt0),(nt1,kt1)
    const u32 addrB0 = sB_a + (u32)(((msel >> 1) * 14 + (msel & 1)) * 128 + rowin * 16);
    const u32 rowBase0 = aW + g * 16;            // element row g   (rtile 0)
    const u32 rowBase1 = aW + 1792 + g * 16;     // element row g+8 (rtile 1)

    // ---- per-element state (2 elements per lane) ----
    const int ebase = blockIdx.x * 64 + w * 16;
    const int e1 = ebase + g, e2 = e1 + 8;
    const float2* x2 = reinterpret_cast<const float2*>(x);
    float2 d0a = x2[0 * BATCH + e1], d1a = x2[1 * BATCH + e1], d2a = x2[2 * BATCH + e1];
    float2 d0b = x2[0 * BATCH + e2], d1b = x2[1 * BATCH + e2], d2b = x2[2 * BATCH + e2];

    float cst[16], hh[16];
#pragma unroll
    for (int i = 0; i < 16; i++) { cst[i] = 0.0f; hh[i] = 0.0f; }

    float2* o2 = reinterpret_cast<float2*>(out);

#pragma unroll 1
    for (int f = 0; f < FOUT; f++) {
#pragma unroll 1
        for (int tt = 0; tt < SEQB; tt++) {
            // stage x (t==0 lanes handle both rows)
            if (t == 0) {
                float2 xa = (tt == 0) ? d0a : (tt == 1) ? d1a : d2a;
                float2 xb = (tt == 0) ? d0b : (tt == 1) ? d1b : d2b;
                u32 hi, lo;
                split2(xa.x, xa.y, hi, lo);
                sts32(rowBase0 + 0, hi);                // k=0,1 (seg0)
                sts32(rowBase0 + 4 * 128 + 8, hi);      // k=36,37 (seg1)
                sts32(rowBase0 + 9 * 128 + 0, lo);      // k=72,73 (seg2)
                split2(xb.x, xb.y, hi, lo);
                sts32(rowBase1 + 0, hi);
                sts32(rowBase1 + 4 * 128 + 8, hi);
                sts32(rowBase1 + 9 * 128 + 0, lo);
            }
            __syncwarp();

            // GEMM: 7 k16-tiles x 16 ntiles
            float d[64];
#pragma unroll
            for (int i = 0; i < 64; i++) d[i] = 0.0f;
#pragma unroll
            for (int m = 0; m < 7; m++) {
                u32 a0, a1, a2, a3;
                LDSM4(a0, a1, a2, a3, addrA0 + m * 256);
#pragma unroll
                for (int q = 0; q < 8; q++) {
                    u32 b0, b1, b2, b3;
                    LDSM4(b0, b1, b2, b3, addrB0 + q * 3584 + m * 256);
                    MMA(&d[(2 * q) * 4],     a0, a1, a2, a3, b0, b1);
                    MMA(&d[(2 * q + 1) * 4], a0, a1, a2, a3, b2, b3);
                }
            }
            __syncwarp();   // all lanes' ldsm done before A staging overwrite

            // epilogue: lane-local gates -> c, h; restage h hi/lo
#pragma unroll
            for (int nt = 0; nt < 4; nt++) {
#pragma unroll
                for (int r = 0; r < 4; r++) {
                    float zi = d[nt * 4 + r];
                    float zf = d[(nt + 4) * 4 + r];
                    float zg = d[(nt + 8) * 4 + r];
                    float zo = d[(nt + 12) * 4 + r];
                    float cn = fmaf(sigmoid_hw(zf), cst[nt * 4 + r],
                                    sigmoid_hw(zi) * tanh_hw(zg));
                    cst[nt * 4 + r] = cn;
                    hh[nt * 4 + r] = sigmoid_hw(zo) * tanh_hw(cn);
                }
                const int k0 = 4 + 8 * nt + 2 * t;          // seg0 slot of unit pair
                const u32 off0 = (u32)(((k0 >> 3) * 128) + (k0 & 7) * 2);
                const int k1 = k0 + 36, k2 = k0 + 72;
                const u32 off1 = (u32)(((k1 >> 3) * 128) + (k1 & 7) * 2);
                const u32 off2 = (u32)(((k2 >> 3) * 128) + (k2 & 7) * 2);
                u32 hi, lo;
                split2(hh[nt * 4 + 0], hh[nt * 4 + 1], hi, lo);   // row g
                sts32(rowBase0 + off0, hi);
                sts32(rowBase0 + off1, hi);
                sts32(rowBase0 + off2, lo);
                split2(hh[nt * 4 + 2], hh[nt * 4 + 3], hi, lo);   // row g+8
                sts32(rowBase1 + off0, hi);
                sts32(rowBase1 + off1, hi);
                sts32(rowBase1 + off2, lo);
            }
        }

        // FC head: per-lane partials over its 8 units, reduce across t group
        float p00 = 0.0f, p01 = 0.0f, p10 = 0.0f, p11 = 0.0f;
#pragma unroll
        for (int nt = 0; nt < 4; nt++) {
            const int j0 = 8 * nt + 2 * t;
            float w00 = sFC[0][j0], w01 = sFC[0][j0 + 1];
            float w10 = sFC[1][j0], w11 = sFC[1][j0 + 1];
            p00 += hh[nt * 4 + 0] * w00 + hh[nt * 4 + 1] * w01;
            p10 += hh[nt * 4 + 0] * w10 + hh[nt * 4 + 1] * w11;
            p01 += hh[nt * 4 + 2] * w00 + hh[nt * 4 + 3] * w01;
            p11 += hh[nt * 4 + 2] * w10 + hh[nt * 4 + 3] * w11;
        }
        p00 += __shfl_xor_sync(0xffffffffu, p00, 1);
        p00 += __shfl_xor_sync(0xffffffffu, p00, 2);
        p10 += __shfl_xor_sync(0xffffffffu, p10, 1);
        p10 += __shfl_xor_sync(0xffffffffu, p10, 2);
        p01 += __shfl_xor_sync(0xffffffffu, p01, 1);
        p01 += __shfl_xor_sync(0xffffffffu, p01, 2);
        p11 += __shfl_xor_sync(0xffffffffu, p11, 1);
        p11 += __shfl_xor_sync(0xffffffffu, p11, 2);

        float2 oa = make_float2(sFCb2[0] + p00, sFCb2[1] + p10);
        float2 ob = make_float2(sFCb2[0] + p01, sFCb2[1] + p11);
        if (t == 0) {
            o2[f * BATCH + e1] = oa;
            o2[f * BATCH + e2] = ob;
        }
        // window: data <- [data[2], data[1], output]
        d0a = d2a; d2a = oa;
        d0b = d2b; d2b = ob;
    }
}

extern "C" void kernel_launch(void* const* d_in, const int* in_sizes, int n_in,
                              void* d_out, int out_size) {
    const float* x    = (const float*)d_in[0];
    const float* W_ih = (const float*)d_in[1];
    const float* W_hh = (const float*)d_in[2];
    const float* b_ih = (const float*)d_in[3];
    const float* b_hh = (const float*)d_in[4];
    const float* W_fc = (const float*)d_in[5];
    const float* b_fc = (const float*)d_in[6];
    float* out = (float*)d_out;

    dim3 grid(BATCH / 64);   // 8192 CTAs x 4 warps x 16 elements
    lstm_mma_kernel<<<grid, THREADS>>>(x, W_ih, W_hh, b_ih, b_hh, W_fc, b_fc, out);
}